// round 11
// baseline (speedup 1.0000x reference)
#include <cuda_runtime.h>
#include <cstdint>

// Sparse 3D conv via warp-level fp16 mma.sync (m16n8k16), single pass.
// R11: feats pre-converted to fp16 by a prep kernel, so a gathered 16B chunk
// IS the lane's A-fragment (K-permutation baked into B prep). Hot loop has
// zero converts, 2 gather LDG.128 + 8 B LDG.128 + 16 MMA per offset, ~64 regs
// -> 4 blocks x 256 thr per SM (occ ~50%). R6-style rolling idx pipeline.

static constexpr int kMVox = 100000;
static constexpr int kNVox = 200000;
static constexpr int kKVol = 27;
static constexpr int kCIn  = 32;
static constexpr int kCOut = 64;
static constexpr int M_TILE = 128;     // 8 warps x 16 rows

// feats converted to f16, channel-contiguous: [n][c], 64B per row
__device__ __align__(16) unsigned short g_f16[(size_t)kNVox * kCIn];

// B fragments, fp16, fragment-order with K-permutation:
// [koff][nb][lane] -> uint4 {w0..w3}, word j = f16x2(W[8t+2j][n], W[8t+2j+1][n])
__device__ __align__(16) uint4 g_bfrag[kKVol * 8 * 32];

__device__ __forceinline__ unsigned f16x2(float x, float y) {
    unsigned r;
    asm("cvt.rn.f16x2.f32 %0, %1, %2;" : "=r"(r) : "f"(y), "f"(x));  // x -> low half
    return r;
}

__global__ void prep_feats_kernel(const float* __restrict__ feats) {
    size_t i = (size_t)blockIdx.x * blockDim.x + threadIdx.x;   // one uint4 out
    if (i >= (size_t)kNVox * kCIn / 8) return;
    const float4* src = (const float4*)feats + 2 * i;
    float4 v0 = src[0], v1 = src[1];
    uint4 o;
    o.x = f16x2(v0.x, v0.y);
    o.y = f16x2(v0.z, v0.w);
    o.z = f16x2(v1.x, v1.y);
    o.w = f16x2(v1.z, v1.w);
    ((uint4*)g_f16)[i] = o;
}

__global__ void prep_kernel(const float* __restrict__ kw) {
    int koff = blockIdx.x, tid = threadIdx.x;       // 27 x 256
    int nb = tid >> 5, lane = tid & 31;
    int g = lane >> 2, t = lane & 3;
    int n = nb * 8 + g;
    const float* W = kw + koff * kCIn * kCOut;      // W[i][n]
    uint4 v;
    v.x = f16x2(W[(8 * t + 0) * kCOut + n], W[(8 * t + 1) * kCOut + n]);
    v.y = f16x2(W[(8 * t + 2) * kCOut + n], W[(8 * t + 3) * kCOut + n]);
    v.z = f16x2(W[(8 * t + 4) * kCOut + n], W[(8 * t + 5) * kCOut + n]);
    v.w = f16x2(W[(8 * t + 6) * kCOut + n], W[(8 * t + 7) * kCOut + n]);
    g_bfrag[(koff * 8 + nb) * 32 + lane] = v;
}

__device__ __forceinline__ void mma16816(float* d,
                                         unsigned a0, unsigned a1,
                                         unsigned a2, unsigned a3,
                                         unsigned b0, unsigned b1) {
    asm volatile(
        "mma.sync.aligned.m16n8k16.row.col.f32.f16.f16.f32 "
        "{%0,%1,%2,%3}, {%4,%5,%6,%7}, {%8,%9}, {%0,%1,%2,%3};"
        : "+f"(d[0]), "+f"(d[1]), "+f"(d[2]), "+f"(d[3])
        : "r"(a0), "r"(a1), "r"(a2), "r"(a3), "r"(b0), "r"(b1));
}

__global__ __launch_bounds__(256, 4)
void conv_hmma_kernel(const int* __restrict__ in_idx,
                      const int* __restrict__ mask,
                      float*     __restrict__ out) {
    const int w = threadIdx.x >> 5, lane = threadIdx.x & 31;
    const int g = lane >> 2, t = lane & 3;
    const int mbase = blockIdx.x * M_TILE + w * 16;
    const int mA = mbase + g;        // fragment rows g
    const int mB = mbase + g + 8;    // fragment rows g+8
    const bool vA = mA < kMVox, vB = mB < kMVox;

    // masked idx pair for offset k (independent loads, select after)
    auto ldidx = [&](int k, int& o0, int& o1) {
        size_t off = (size_t)k * kMVox;
        int mk0 = vA ? mask[off + mA] : 0;
        int ix0 = vA ? in_idx[off + mA] : 0;
        int mk1 = vB ? mask[off + mB] : 0;
        int ix1 = vB ? in_idx[off + mB] : 0;
        o0 = mk0 ? ix0 : -1;
        o1 = mk1 ? ix1 : -1;
    };
    // lane's fragment chunk from f16 row (16B = frag words for this lane)
    auto ldrow = [&](int iv) -> uint4 {
        const uint4* p = (const uint4*)(g_f16 + (size_t)(iv < 0 ? 0 : iv) * kCIn);
        uint4 z = make_uint4(0u, 0u, 0u, 0u);
        return (iv >= 0) ? p[t] : z;
    };

    float acc[8][4];
#pragma unroll
    for (int i = 0; i < 8; ++i)
#pragma unroll
        for (int j = 0; j < 4; ++j) acc[i][j] = 0.f;

    // --- prologue ---
    int i0, i1;
    ldidx(0, i0, i1);
    uint4 uA = ldrow(i0), uB = ldrow(i1);   // current fragments
    int a0, a1, b0i, b1i;
    ldidx(1, a0, a1);                        // idx for k+1 (ready first)
    ldidx(2, b0i, b1i);                      // idx for k+2 (in flight)

#pragma unroll 1
    for (int koff = 0; koff < kKVol; ++koff) {
        // current fragments (no converts: loaded bits are the f16 pairs)
        unsigned c0 = uA.x, c1 = uB.x, c2 = uA.y, c3 = uB.y;   // ks0
        unsigned d0 = uA.z, d1 = uB.z, d2 = uA.w, d3 = uB.w;   // ks1

        // issue rows for k+1 (cover = full MMA block below)
        if (koff + 1 < kKVol) {
            uA = ldrow(a0);
            uB = ldrow(a1);
        }
        // rotate idx pipeline: a <- b, issue idx for k+3
        a0 = b0i; a1 = b1i;
        if (koff + 3 < kKVol) ldidx(koff + 3, b0i, b1i);

        // --- MMA block: 8 n-blocks x 2 k-steps ---
        const uint4* bp = g_bfrag + (size_t)koff * 8 * 32 + lane;
#pragma unroll
        for (int nb = 0; nb < 8; ++nb) {
            uint4 bw = bp[nb * 32];
            mma16816(acc[nb], c0, c1, c2, c3, bw.x, bw.y);
            mma16816(acc[nb], d0, d1, d2, d3, bw.z, bw.w);
        }
    }

    // store: d0,d1 -> row mA cols nb*8+2t..+1 ; d2,d3 -> row mB
#pragma unroll
    for (int nb = 0; nb < 8; ++nb) {
        int n = nb * 8 + 2 * t;
        if (vA)
            *(float2*)(out + (size_t)mA * kCOut + n) = make_float2(acc[nb][0], acc[nb][1]);
        if (vB)
            *(float2*)(out + (size_t)mB * kCOut + n) = make_float2(acc[nb][2], acc[nb][3]);
    }
}

extern "C" void kernel_launch(void* const* d_in, const int* in_sizes, int n_in,
                              void* d_out, int out_size) {
    const float* feats  = (const float*)d_in[0];
    const float* kernel = (const float*)d_in[1];
    const int*   in_idx = (const int*)d_in[2];
    const int*   maskp  = (const int*)d_in[3];
    float*       out    = (float*)d_out;
    (void)in_sizes; (void)n_in; (void)out_size;

    prep_feats_kernel<<<(kNVox * kCIn / 8 + 255) / 256, 256>>>(feats);
    prep_kernel<<<kKVol, 256>>>(kernel);
    int grid = (kMVox + M_TILE - 1) / M_TILE;   // 782
    conv_hmma_kernel<<<grid, 256>>>(in_idx, maskp, out);
}

// round 12
// speedup vs baseline: 1.9248x; 1.9248x over previous
#include <cuda_runtime.h>
#include <cstdint>

// Sparse 3D conv via warp-level fp16 mma.sync (m16n8k16), single pass.
// R12 = R11 (feats pre-converted to fp16; gathered 16B chunk IS the lane's
// A-fragment; zero converts in hot loop) with the register cap restored to
// launch_bounds(256,3) — R11's (256,4) forced a 64-reg cap and spilled the
// inner loop to local memory (2x regression).

static constexpr int kMVox = 100000;
static constexpr int kNVox = 200000;
static constexpr int kKVol = 27;
static constexpr int kCIn  = 32;
static constexpr int kCOut = 64;
static constexpr int M_TILE = 128;     // 8 warps x 16 rows

// feats converted to f16, channel-contiguous: [n][c], 64B per row
__device__ __align__(16) unsigned short g_f16[(size_t)kNVox * kCIn];

// B fragments, fp16, fragment-order with K-permutation:
// [koff][nb][lane] -> uint4 {w0..w3}, word j = f16x2(W[8t+2j][n], W[8t+2j+1][n])
__device__ __align__(16) uint4 g_bfrag[kKVol * 8 * 32];

__device__ __forceinline__ unsigned f16x2(float x, float y) {
    unsigned r;
    asm("cvt.rn.f16x2.f32 %0, %1, %2;" : "=r"(r) : "f"(y), "f"(x));  // x -> low half
    return r;
}

__global__ void prep_feats_kernel(const float* __restrict__ feats) {
    size_t i = (size_t)blockIdx.x * blockDim.x + threadIdx.x;   // one uint4 out
    if (i >= (size_t)kNVox * kCIn / 8) return;
    const float4* src = (const float4*)feats + 2 * i;
    float4 v0 = src[0], v1 = src[1];
    uint4 o;
    o.x = f16x2(v0.x, v0.y);
    o.y = f16x2(v0.z, v0.w);
    o.z = f16x2(v1.x, v1.y);
    o.w = f16x2(v1.z, v1.w);
    ((uint4*)g_f16)[i] = o;
}

__global__ void prep_kernel(const float* __restrict__ kw) {
    int koff = blockIdx.x, tid = threadIdx.x;       // 27 x 256
    int nb = tid >> 5, lane = tid & 31;
    int g = lane >> 2, t = lane & 3;
    int n = nb * 8 + g;
    const float* W = kw + koff * kCIn * kCOut;      // W[i][n]
    uint4 v;
    v.x = f16x2(W[(8 * t + 0) * kCOut + n], W[(8 * t + 1) * kCOut + n]);
    v.y = f16x2(W[(8 * t + 2) * kCOut + n], W[(8 * t + 3) * kCOut + n]);
    v.z = f16x2(W[(8 * t + 4) * kCOut + n], W[(8 * t + 5) * kCOut + n]);
    v.w = f16x2(W[(8 * t + 6) * kCOut + n], W[(8 * t + 7) * kCOut + n]);
    g_bfrag[(koff * 8 + nb) * 32 + lane] = v;
}

__device__ __forceinline__ void mma16816(float* d,
                                         unsigned a0, unsigned a1,
                                         unsigned a2, unsigned a3,
                                         unsigned b0, unsigned b1) {
    asm volatile(
        "mma.sync.aligned.m16n8k16.row.col.f32.f16.f16.f32 "
        "{%0,%1,%2,%3}, {%4,%5,%6,%7}, {%8,%9}, {%0,%1,%2,%3};"
        : "+f"(d[0]), "+f"(d[1]), "+f"(d[2]), "+f"(d[3])
        : "r"(a0), "r"(a1), "r"(a2), "r"(a3), "r"(b0), "r"(b1));
}

__global__ __launch_bounds__(256, 3)
void conv_hmma_kernel(const int* __restrict__ in_idx,
                      const int* __restrict__ mask,
                      float*     __restrict__ out) {
    const int w = threadIdx.x >> 5, lane = threadIdx.x & 31;
    const int g = lane >> 2, t = lane & 3;
    const int mbase = blockIdx.x * M_TILE + w * 16;
    const int mA = mbase + g;        // fragment rows g
    const int mB = mbase + g + 8;    // fragment rows g+8
    const bool vA = mA < kMVox, vB = mB < kMVox;

    // masked idx pair for offset k (independent loads, select after)
    auto ldidx = [&](int k, int& o0, int& o1) {
        size_t off = (size_t)k * kMVox;
        int mk0 = vA ? mask[off + mA] : 0;
        int ix0 = vA ? in_idx[off + mA] : 0;
        int mk1 = vB ? mask[off + mB] : 0;
        int ix1 = vB ? in_idx[off + mB] : 0;
        o0 = mk0 ? ix0 : -1;
        o1 = mk1 ? ix1 : -1;
    };
    // lane's fragment chunk from f16 row (16B = frag words for this lane)
    auto ldrow = [&](int iv) -> uint4 {
        const uint4* p = (const uint4*)(g_f16 + (size_t)(iv < 0 ? 0 : iv) * kCIn);
        uint4 z = make_uint4(0u, 0u, 0u, 0u);
        return (iv >= 0) ? p[t] : z;
    };

    float acc[8][4];
#pragma unroll
    for (int i = 0; i < 8; ++i)
#pragma unroll
        for (int j = 0; j < 4; ++j) acc[i][j] = 0.f;

    // --- prologue ---
    int i0, i1;
    ldidx(0, i0, i1);
    uint4 uA = ldrow(i0), uB = ldrow(i1);   // current fragments
    int a0, a1, b0i, b1i;
    ldidx(1, a0, a1);                        // idx for k+1 (ready first)
    ldidx(2, b0i, b1i);                      // idx for k+2 (in flight)

#pragma unroll 1
    for (int koff = 0; koff < kKVol; ++koff) {
        // current fragments (no converts: loaded bits are the f16 pairs)
        unsigned c0 = uA.x, c1 = uB.x, c2 = uA.y, c3 = uB.y;   // ks0
        unsigned d0 = uA.z, d1 = uB.z, d2 = uA.w, d3 = uB.w;   // ks1

        // issue rows for k+1 (cover = full MMA block below)
        if (koff + 1 < kKVol) {
            uA = ldrow(a0);
            uB = ldrow(a1);
        }
        // rotate idx pipeline: a <- b, issue idx for k+3
        a0 = b0i; a1 = b1i;
        if (koff + 3 < kKVol) ldidx(koff + 3, b0i, b1i);

        // --- MMA block: 8 n-blocks x 2 k-steps ---
        const uint4* bp = g_bfrag + (size_t)koff * 8 * 32 + lane;
#pragma unroll
        for (int nb = 0; nb < 8; ++nb) {
            uint4 bw = bp[nb * 32];
            mma16816(acc[nb], c0, c1, c2, c3, bw.x, bw.y);
            mma16816(acc[nb], d0, d1, d2, d3, bw.z, bw.w);
        }
    }

    // store: d0,d1 -> row mA cols nb*8+2t..+1 ; d2,d3 -> row mB
#pragma unroll
    for (int nb = 0; nb < 8; ++nb) {
        int n = nb * 8 + 2 * t;
        if (vA)
            *(float2*)(out + (size_t)mA * kCOut + n) = make_float2(acc[nb][0], acc[nb][1]);
        if (vB)
            *(float2*)(out + (size_t)mB * kCOut + n) = make_float2(acc[nb][2], acc[nb][3]);
    }
}

extern "C" void kernel_launch(void* const* d_in, const int* in_sizes, int n_in,
                              void* d_out, int out_size) {
    const float* feats  = (const float*)d_in[0];
    const float* kernel = (const float*)d_in[1];
    const int*   in_idx = (const int*)d_in[2];
    const int*   maskp  = (const int*)d_in[3];
    float*       out    = (float*)d_out;
    (void)in_sizes; (void)n_in; (void)out_size;

    prep_feats_kernel<<<(kNVox * kCIn / 8 + 255) / 256, 256>>>(feats);
    prep_kernel<<<kKVol, 256>>>(kernel);
    int grid = (kMVox + M_TILE - 1) / M_TILE;   // 782
    conv_hmma_kernel<<<grid, 256>>>(in_idx, maskp, out);
}